// round 9
// baseline (speedup 1.0000x reference)
#include <cuda_runtime.h>
#include <cuda_bf16.h>
#include <cstddef>
#include <cstdint>

#define N_PTS   20000
#define E_EDGES 320000
#define KNN     16
#define FEAT    64
#define R_REP   4

// ---------------- scratch (static device globals; allocation-free) ----------
__device__ float         g_x1[(size_t)N_PTS * FEAT];   // 5.12 MB
__device__ float         g_sq[N_PTS];
__device__ __nv_bfloat16 g_xb[(size_t)N_PTS * 128];    // 5.12 MB: [h(64), l(64)]
__device__ int           g_nbr[(size_t)N_PTS * KNN];   // 1.28 MB
__device__ float         g_x2[(size_t)N_PTS * FEAT];   // 5.12 MB

// ---------------- helpers ---------------------------------------------------
__device__ __forceinline__ unsigned enc_f(float f) {
    unsigned u = __float_as_uint(f);
    return (u & 0x80000000u) ? ~u : (u | 0x80000000u);
}
__device__ __forceinline__ uint32_t smem_u32(const void* p) {
    uint32_t a;
    asm("{ .reg .u64 t; cvta.to.shared.u64 t, %1; cvt.u32.u64 %0, t; }"
        : "=r"(a) : "l"(p));
    return a;
}
__device__ __forceinline__ void ldsm4(uint32_t* r, uint32_t addr) {
    asm volatile("ldmatrix.sync.aligned.m8n8.x4.shared.b16 {%0,%1,%2,%3}, [%4];"
        : "=r"(r[0]), "=r"(r[1]), "=r"(r[2]), "=r"(r[3]) : "r"(addr));
}
__device__ __forceinline__ void mma16816(float* c, const uint32_t* a,
                                         uint32_t b0, uint32_t b1) {
    asm volatile(
        "mma.sync.aligned.m16n8k16.row.col.f32.bf16.bf16.f32 "
        "{%0,%1,%2,%3}, {%4,%5,%6,%7}, {%8,%9}, {%0,%1,%2,%3};"
        : "+f"(c[0]), "+f"(c[1]), "+f"(c[2]), "+f"(c[3])
        : "r"(a[0]), "r"(a[1]), "r"(a[2]), "r"(a[3]), "r"(b0), "r"(b1));
}

// ---------------- zero x1 ----------------------------------------------------
__global__ void k_zero_x1() {
    int i = blockIdx.x * blockDim.x + threadIdx.x;
    if (i < N_PTS * FEAT) g_x1[i] = 0.f;
}

// ---------------- stage 1: edge MLP (6->64->64, ReLU) + segment_max ---------
__global__ void __launch_bounds__(256) k_edge(
    const float* __restrict__ pts, const int* __restrict__ ei,
    const float* __restrict__ W1a, const float* __restrict__ b1a,
    const float* __restrict__ W1b, const float* __restrict__ b1b)
{
    __shared__ float sW1a[6 * 64];
    __shared__ float sW1b[64 * 64];
    __shared__ float sh1[64][66];
    int t = threadIdx.x;
    for (int i = t; i < 6 * 64 / 4; i += 256)
        ((float4*)sW1a)[i] = ((const float4*)W1a)[i];
    for (int i = t; i < 64 * 64 / 4; i += 256)
        ((float4*)sW1b)[i] = ((const float4*)W1b)[i];

    int e  = t >> 2;
    int o0 = (t & 3) * 16;
    int eg = blockIdx.x * 64 + e;
    int s  = ei[eg];
    int d  = ei[E_EDGES + eg];
    float xi0 = pts[d * 3 + 0], xi1 = pts[d * 3 + 1], xi2 = pts[d * 3 + 2];
    float in6[6];
    in6[0] = xi0; in6[1] = xi1; in6[2] = xi2;
    in6[3] = pts[s * 3 + 0] - xi0;
    in6[4] = pts[s * 3 + 1] - xi1;
    in6[5] = pts[s * 3 + 2] - xi2;
    __syncthreads();

    float acc[16];
#pragma unroll
    for (int u = 0; u < 16; u++) acc[u] = __ldg(&b1a[o0 + u]);
#pragma unroll
    for (int k = 0; k < 6; k++) {
        float x = in6[k];
#pragma unroll
        for (int v = 0; v < 4; v++) {
            float4 w = *(const float4*)&sW1a[k * 64 + o0 + v * 4];
            acc[v*4+0] = fmaf(x, w.x, acc[v*4+0]);
            acc[v*4+1] = fmaf(x, w.y, acc[v*4+1]);
            acc[v*4+2] = fmaf(x, w.z, acc[v*4+2]);
            acc[v*4+3] = fmaf(x, w.w, acc[v*4+3]);
        }
    }
#pragma unroll
    for (int u = 0; u < 16; u++) sh1[e][o0 + u] = fmaxf(acc[u], 0.f);
    __syncthreads();

#pragma unroll
    for (int u = 0; u < 16; u++) acc[u] = __ldg(&b1b[o0 + u]);
#pragma unroll 8
    for (int k = 0; k < 64; k++) {
        float h = sh1[e][k];
#pragma unroll
        for (int v = 0; v < 4; v++) {
            float4 w = *(const float4*)&sW1b[k * 64 + o0 + v * 4];
            acc[v*4+0] = fmaf(h, w.x, acc[v*4+0]);
            acc[v*4+1] = fmaf(h, w.y, acc[v*4+1]);
            acc[v*4+2] = fmaf(h, w.z, acc[v*4+2]);
            acc[v*4+3] = fmaf(h, w.w, acc[v*4+3]);
        }
    }
    int base = d * FEAT + o0;
#pragma unroll
    for (int u = 0; u < 16; u++) {
        float v = fmaxf(acc[u], 0.f);   // >= 0 : int order == float order
        atomicMax((int*)(g_x1 + base + u), __float_as_int(v));
    }
}

// ---------------- squared norms + bf16 hi/lo split ---------------------------
__global__ void k_split() {
    int i = blockIdx.x * blockDim.x + threadIdx.x;
    if (i >= N_PTS) return;
    const float4* r = (const float4*)(g_x1 + (size_t)i * 64);
    __nv_bfloat16* dst = g_xb + (size_t)i * 128;
    float s = 0.f;
#pragma unroll
    for (int c = 0; c < 16; c++) {
        float4 v = r[c];
        s += v.x * v.x + v.y * v.y + v.z * v.z + v.w * v.w;
        float xs[4] = {v.x, v.y, v.z, v.w};
#pragma unroll
        for (int u = 0; u < 4; u++) {
            __nv_bfloat16 h = __float2bfloat16_rn(xs[u]);
            __nv_bfloat16 l = __float2bfloat16_rn(xs[u] - __bfloat162float(h));
            dst[c * 4 + u]      = h;
            dst[64 + c * 4 + u] = l;
        }
    }
    g_sq[i] = s;
}

// ---------------- stage 2: HMMA bf16 distance GEMM + fused top-16 -----------
// 128 threads / 4 warps; 128 queries/block (warp owns 32); candidate tile 64;
// K = 192 via hi/lo split (A rows [h,h,l], B rows [h,l,h]).
#define QB      128
#define NB      64
#define NTILES  ((N_PTS + NB - 1) / NB)     // 313
#define KSTEPS  12
#define STRB    400                          // bytes per smem row (200 bf16)
#define A_OFF   0
#define B_OFF   (QB * STRB)                  // 51200
#define DS_OFF  (B_OFF + NB * STRB)          // 76800
#define DS_STR  34                           // floats per scratch row
#define DS_WARP (32 * DS_STR * 4)            // 4352 bytes
#define SSQ_OFF (DS_OFF + 4 * DS_WARP)       // 94208
#define KNN_SMEM (SSQ_OFF + NB * 4)          // 94464

__global__ void __launch_bounds__(128, 1) k_knn3() {
    extern __shared__ char smem[];
    const uint32_t sbase = smem_u32(smem);
    float* Dsw   = (float*)(smem + DS_OFF + (threadIdx.x >> 5) * DS_WARP);
    float* ssq_s = (float*)(smem + SSQ_OFF);

    int t    = threadIdx.x;
    int w    = t >> 5;
    int lane = t & 31;
    int qb   = blockIdx.x * QB;

    // ---- stage A once: row r <- query qb+r, layout [h, h, l], stride 400B
    {
        int q = min(qb + t, N_PTS - 1);
        const uint4* s4 = (const uint4*)(g_xb + (size_t)q * 128);
        uint4* d4 = (uint4*)(smem + A_OFF + t * STRB);
        uint4 hbuf[8];
#pragma unroll
        for (int i = 0; i < 8; i++) hbuf[i] = s4[i];
#pragma unroll
        for (int i = 0; i < 8; i++) d4[i] = hbuf[i];
#pragma unroll
        for (int i = 0; i < 8; i++) d4[8 + i] = hbuf[i];
#pragma unroll
        for (int i = 0; i < 8; i++) d4[16 + i] = s4[8 + i];
    }

    // ---- per-lane ldmatrix base addresses
    int seg = lane >> 3, l7 = lane & 7;
    uint32_t aAddr[2], bAddr[4];
#pragma unroll
    for (int mt = 0; mt < 2; mt++) {
        int row = w * 32 + mt * 16 + (seg & 1) * 8 + l7;
        aAddr[mt] = sbase + A_OFF + row * STRB + (seg >> 1) * 16;
    }
#pragma unroll
    for (int ntp = 0; ntp < 4; ntp++) {
        int row = ntp * 16 + (seg >> 1) * 8 + l7;
        bAddr[ntp] = sbase + B_OFF + row * STRB + (seg & 1) * 16;
    }

    unsigned long long lst[16];
#pragma unroll
    for (int i = 0; i < 16; i++) lst[i] = 0xFFFFFFFFFFFFFFFFull;
    float thr = __int_as_float(0x7f800000);   // +inf until list is full

    int gid = lane >> 2, t4 = lane & 3;

    for (int tt = 0; tt < NTILES; tt++) {
        int j0 = tt * NB;
        __syncthreads();              // everyone done reading previous B / ssq
        {   // stage B tile: row r <- cand j0+r, layout [h, l, h]
            int r = t >> 1, hf = t & 1;
            int j = min(j0 + r, N_PTS - 1);
            const uint4* s4 = (const uint4*)(g_xb + (size_t)j * 128);
            uint4* d4 = (uint4*)(smem + B_OFF + r * STRB + hf * 192);
            if (hf == 0) {
#pragma unroll
                for (int i = 0; i < 12; i++) d4[i] = s4[i];       // elems 0-95
            } else {
#pragma unroll
                for (int i = 0; i < 4; i++) d4[i] = s4[12 + i];   // 96-127 (l)
#pragma unroll
                for (int i = 0; i < 8; i++) d4[4 + i] = s4[i];    // 128-191 (h)
            }
            if (t < NB) ssq_s[t] = g_sq[min(j0 + t, N_PTS - 1)];
        }
        __syncthreads();

        float acc[2][8][4];
#pragma unroll
        for (int mt = 0; mt < 2; mt++)
#pragma unroll
            for (int nt = 0; nt < 8; nt++)
#pragma unroll
                for (int u = 0; u < 4; u++) acc[mt][nt][u] = 0.f;

#pragma unroll
        for (int ks = 0; ks < KSTEPS; ks++) {
            uint32_t koff = ks * 32;
            uint32_t a[2][4], b[4][4];
#pragma unroll
            for (int mt = 0; mt < 2; mt++) ldsm4(a[mt], aAddr[mt] + koff);
#pragma unroll
            for (int ntp = 0; ntp < 4; ntp++) ldsm4(b[ntp], bAddr[ntp] + koff);
#pragma unroll
            for (int mt = 0; mt < 2; mt++)
#pragma unroll
                for (int nt = 0; nt < 8; nt++)
                    mma16816(acc[mt][nt], a[mt],
                             b[nt >> 1][(nt & 1) * 2],
                             b[nt >> 1][(nt & 1) * 2 + 1]);
        }

        // ---- epilogue: two 32-col halves through per-warp smem scratch
#pragma unroll
        for (int half = 0; half < 2; half++) {
#pragma unroll
            for (int nt4 = 0; nt4 < 4; nt4++) {
                int nt = half * 4 + nt4;
#pragma unroll
                for (int mt = 0; mt < 2; mt++) {
                    int r0 = mt * 16 + gid;
                    float* c = acc[mt][nt];
                    *(float2*)&Dsw[r0 * DS_STR + nt4 * 8 + t4 * 2] =
                        make_float2(c[0], c[1]);
                    *(float2*)&Dsw[(r0 + 8) * DS_STR + nt4 * 8 + t4 * 2] =
                        make_float2(c[2], c[3]);
                }
            }
            __syncwarp();
            int jbase = j0 + half * 32;
            int cmax  = min(32, N_PTS - jbase);
#pragma unroll
            for (int c4 = 0; c4 < 8; c4++) {
                float2 dv0 = *(const float2*)&Dsw[lane * DS_STR + c4 * 4];
                float2 dv1 = *(const float2*)&Dsw[lane * DS_STR + c4 * 4 + 2];
                float dd[4] = {dv0.x, dv0.y, dv1.x, dv1.y};
#pragma unroll
                for (int u = 0; u < 4; u++) {
                    int cc = c4 * 4 + u;
                    if (cc >= cmax) break;
                    float d = fmaf(-2.f, dd[u], ssq_s[half * 32 + cc]);
                    if (d <= thr) {
                        unsigned long long key =
                            ((unsigned long long)enc_f(d) << 32)
                            | (unsigned)(jbase + cc);
                        if (key < lst[15]) {
                            lst[15] = key;
#pragma unroll
                            for (int p = 15; p >= 1; p--) {
                                if (lst[p] < lst[p-1]) {
                                    unsigned long long tmp = lst[p];
                                    lst[p] = lst[p-1]; lst[p-1] = tmp;
                                }
                            }
                            unsigned hi = (unsigned)(lst[15] >> 32);
                            thr = (hi == 0xFFFFFFFFu)
                                ? __int_as_float(0x7f800000)      // not full yet
                                : ((hi & 0x80000000u)
                                       ? __uint_as_float(hi & 0x7fffffffu)
                                       : __uint_as_float(~hi));
                        }
                    }
                }
            }
            __syncwarp();
        }
    }

    int q = qb + w * 32 + lane;
    if (q < N_PTS) {
#pragma unroll
        for (int i = 0; i < 16; i++)
            g_nbr[(size_t)q * 16 + i] = (int)(lst[i] & 0xffffffffu);
    }
}

// ---------------- stage 3: pair MLP (128->64->64, ReLU) + max over K --------
__global__ void __launch_bounds__(256) k_pair(
    const float* __restrict__ W2a, const float* __restrict__ b2a,
    const float* __restrict__ W2b, const float* __restrict__ b2b)
{
    __shared__ float sT[128][66];
    __shared__ float sW[32][64];

    int t = threadIdx.x;
    int r = t >> 2, part = t & 3, o0 = part * 16;
    size_t row = (size_t)blockIdx.x * 64 + r;
    int n = (int)(row >> 4);
    int j = g_nbr[row];

    {
        const float4* xi4 = (const float4*)(g_x1 + (size_t)n * 64);
        const float4* xj4 = (const float4*)(g_x1 + (size_t)j * 64);
#pragma unroll
        for (int i = 0; i < 4; i++) {
            float4 a = xi4[part * 4 + i];
            float4 b = xj4[part * 4 + i];
            int k = (part * 4 + i) * 4;
            sT[k+0][r] = a.x;  sT[k+1][r] = a.y;  sT[k+2][r] = a.z;  sT[k+3][r] = a.w;
            sT[64+k+0][r] = b.x - a.x; sT[64+k+1][r] = b.y - a.y;
            sT[64+k+2][r] = b.z - a.z; sT[64+k+3][r] = b.w - a.w;
        }
    }

    float acc[16];
#pragma unroll
    for (int u = 0; u < 16; u++) acc[u] = __ldg(&b2a[o0 + u]);

    for (int ch = 0; ch < 4; ch++) {
        __syncthreads();
        {
            const float4* wsrc = (const float4*)(W2a) + ch * 512;
            float4* wdst = (float4*)sW;
            wdst[t] = wsrc[t];
            wdst[t + 256] = wsrc[t + 256];
        }
        __syncthreads();
#pragma unroll 8
        for (int kk = 0; kk < 32; kk++) {
            float x = sT[ch * 32 + kk][r];
#pragma unroll
            for (int v = 0; v < 4; v++) {
                float4 w = *(const float4*)&sW[kk][o0 + v * 4];
                acc[v*4+0] = fmaf(x, w.x, acc[v*4+0]);
                acc[v*4+1] = fmaf(x, w.y, acc[v*4+1]);
                acc[v*4+2] = fmaf(x, w.z, acc[v*4+2]);
                acc[v*4+3] = fmaf(x, w.w, acc[v*4+3]);
            }
        }
    }
    __syncthreads();
#pragma unroll
    for (int u = 0; u < 16; u++) sT[o0 + u][r] = fmaxf(acc[u], 0.f);

#pragma unroll
    for (int u = 0; u < 16; u++) acc[u] = __ldg(&b2b[o0 + u]);
    for (int ch = 0; ch < 2; ch++) {
        __syncthreads();
        {
            const float4* wsrc = (const float4*)(W2b) + ch * 512;
            float4* wdst = (float4*)sW;
            wdst[t] = wsrc[t];
            wdst[t + 256] = wsrc[t + 256];
        }
        __syncthreads();
#pragma unroll 8
        for (int kk = 0; kk < 32; kk++) {
            float x = sT[ch * 32 + kk][r];
#pragma unroll
            for (int v = 0; v < 4; v++) {
                float4 w = *(const float4*)&sW[kk][o0 + v * 4];
                acc[v*4+0] = fmaf(x, w.x, acc[v*4+0]);
                acc[v*4+1] = fmaf(x, w.y, acc[v*4+1]);
                acc[v*4+2] = fmaf(x, w.z, acc[v*4+2]);
                acc[v*4+3] = fmaf(x, w.w, acc[v*4+3]);
            }
        }
    }
    __syncthreads();
#pragma unroll
    for (int u = 0; u < 16; u++) sT[o0 + u][r] = fmaxf(acc[u], 0.f);
    __syncthreads();

    {
        int p = t >> 6, f = t & 63;
        float m = sT[f][p * 16];
#pragma unroll
        for (int kk = 1; kk < 16; kk++) m = fmaxf(m, sT[f][p * 16 + kk]);
        g_x2[((size_t)blockIdx.x * 4 + p) * 64 + f] = m;
    }
}

// ---------------- stage 4: fused head (We_r -> Wp -> relu(Wr1) -> Wr2) ------
__global__ void __launch_bounds__(256) k_head(
    const float* __restrict__ We,  const float* __restrict__ be,
    const float* __restrict__ Wp,  const float* __restrict__ bp,
    const float* __restrict__ Wr1, const float* __restrict__ br1,
    const float* __restrict__ Wr2, const float* __restrict__ br2,
    float* __restrict__ out)
{
    __shared__ float sT[64][66];
    __shared__ float sW[64][64];

    int t = threadIdx.x;
    int r = t >> 2, part = t & 3, o0 = part * 16;
    int rr = blockIdx.y;
    int n  = blockIdx.x * 64 + r;
    int nl = min(n, N_PTS - 1);

    {
        const float4* src = (const float4*)(g_x2 + (size_t)nl * 64);
#pragma unroll
        for (int i = 0; i < 4; i++) {
            float4 v = src[part * 4 + i];
            int k = (part * 4 + i) * 4;
            sT[k+0][r] = v.x; sT[k+1][r] = v.y; sT[k+2][r] = v.z; sT[k+3][r] = v.w;
        }
    }
    {
        int kr = t >> 2, q = t & 3;
#pragma unroll
        for (int i = 0; i < 4; i++)
            *(float4*)&sW[kr][q * 16 + i * 4] =
                *(const float4*)(We + (size_t)kr * 256 + rr * 64 + q * 16 + i * 4);
    }
    __syncthreads();

    float acc[16];
#pragma unroll
    for (int u = 0; u < 16; u++) acc[u] = __ldg(&be[rr * 64 + o0 + u]);
#pragma unroll 8
    for (int k = 0; k < 64; k++) {
        float x = sT[k][r];
#pragma unroll
        for (int v = 0; v < 4; v++) {
            float4 w = *(const float4*)&sW[k][o0 + v * 4];
            acc[v*4+0] = fmaf(x, w.x, acc[v*4+0]);
            acc[v*4+1] = fmaf(x, w.y, acc[v*4+1]);
            acc[v*4+2] = fmaf(x, w.z, acc[v*4+2]);
            acc[v*4+3] = fmaf(x, w.w, acc[v*4+3]);
        }
    }
    __syncthreads();
#pragma unroll
    for (int u = 0; u < 16; u++) sT[o0 + u][r] = acc[u];
    {
        int kr = t >> 2, q = t & 3;
#pragma unroll
        for (int i = 0; i < 4; i++)
            *(float4*)&sW[kr][q * 16 + i * 4] =
                *(const float4*)(Wp + (size_t)kr * 64 + q * 16 + i * 4);
    }
    __syncthreads();

#pragma unroll
    for (int u = 0; u < 16; u++) acc[u] = __ldg(&bp[o0 + u]);
#pragma unroll 8
    for (int k = 0; k < 64; k++) {
        float x = sT[k][r];
#pragma unroll
        for (int v = 0; v < 4; v++) {
            float4 w = *(const float4*)&sW[k][o0 + v * 4];
            acc[v*4+0] = fmaf(x, w.x, acc[v*4+0]);
            acc[v*4+1] = fmaf(x, w.y, acc[v*4+1]);
            acc[v*4+2] = fmaf(x, w.z, acc[v*4+2]);
            acc[v*4+3] = fmaf(x, w.w, acc[v*4+3]);
        }
    }
    __syncthreads();
#pragma unroll
    for (int u = 0; u < 16; u++) sT[o0 + u][r] = acc[u];
    {
        int kr = t >> 2, q = t & 3;
#pragma unroll
        for (int i = 0; i < 4; i++)
            *(float4*)&sW[kr][q * 16 + i * 4] =
                *(const float4*)(Wr1 + (size_t)kr * 64 + q * 16 + i * 4);
    }
    __syncthreads();

#pragma unroll
    for (int u = 0; u < 16; u++) acc[u] = __ldg(&br1[o0 + u]);
#pragma unroll 8
    for (int k = 0; k < 64; k++) {
        float x = sT[k][r];
#pragma unroll
        for (int v = 0; v < 4; v++) {
            float4 w = *(const float4*)&sW[k][o0 + v * 4];
            acc[v*4+0] = fmaf(x, w.x, acc[v*4+0]);
            acc[v*4+1] = fmaf(x, w.y, acc[v*4+1]);
            acc[v*4+2] = fmaf(x, w.z, acc[v*4+2]);
            acc[v*4+3] = fmaf(x, w.w, acc[v*4+3]);
        }
    }
    __syncthreads();
#pragma unroll
    for (int u = 0; u < 16; u++) sT[o0 + u][r] = fmaxf(acc[u], 0.f);
    if (t < 192) ((float*)sW)[t] = Wr2[t];
    if (t >= 192 && t < 195) ((float*)sW)[t] = br2[t - 192];
    __syncthreads();

    if (part < 3 && n < N_PTS) {
        float y = ((float*)sW)[192 + part];
#pragma unroll 8
        for (int k = 0; k < 64; k++)
            y = fmaf(sT[k][r], ((float*)sW)[k * 3 + part], y);
        out[((size_t)rr * N_PTS + n) * 3 + part] = y;
    }
}

// ---------------- launch -----------------------------------------------------
extern "C" void kernel_launch(void* const* d_in, const int* in_sizes, int n_in,
                              void* d_out, int out_size) {
    const float* pts = (const float*)d_in[0];
    const float* W1a = (const float*)d_in[1];
    const float* b1a = (const float*)d_in[2];
    const float* W1b = (const float*)d_in[3];
    const float* b1b = (const float*)d_in[4];
    const float* W2a = (const float*)d_in[5];
    const float* b2a = (const float*)d_in[6];
    const float* W2b = (const float*)d_in[7];
    const float* b2b = (const float*)d_in[8];
    const float* We  = (const float*)d_in[9];
    const float* be  = (const float*)d_in[10];
    const float* Wp  = (const float*)d_in[11];
    const float* bp  = (const float*)d_in[12];
    const float* Wr1 = (const float*)d_in[13];
    const float* br1 = (const float*)d_in[14];
    const float* Wr2 = (const float*)d_in[15];
    const float* br2 = (const float*)d_in[16];
    const int*   ei  = (const int*)d_in[17];
    float* out = (float*)d_out;

    cudaFuncSetAttribute(k_knn3, cudaFuncAttributeMaxDynamicSharedMemorySize,
                         KNN_SMEM);

    k_zero_x1<<<(N_PTS * FEAT + 255) / 256, 256>>>();
    k_edge<<<E_EDGES / 64, 256>>>(pts, ei, W1a, b1a, W1b, b1b);
    k_split<<<(N_PTS + 255) / 256, 256>>>();
    k_knn3<<<(N_PTS + QB - 1) / QB, 128, KNN_SMEM>>>();
    k_pair<<<(N_PTS * KNN) / 64, 256>>>(W2a, b2a, W2b, b2b);
    k_head<<<dim3((N_PTS + 63) / 64, R_REP), 256>>>(We, be, Wp, bp, Wr1, br1,
                                                    Wr2, br2, out);
}